// round 1
// baseline (speedup 1.0000x reference)
#include <cuda_runtime.h>

#define TPB 256
#define T_ 200
#define D_ 64
#define H1_ 80
#define H2_ 40
#define C_ 64
#define KSTRIDE 204

// shared-memory float offsets
#define KST   0
#define H1T   (KST + D_*KSTRIDE)        // 13056
#define MW    (H1T + H1_*T_)            // 29056  (M during GEMM1, cate acc later)
#define W2S   (MW + D_*H1_)             // 34176
#define QA    (W2S + H1_*H2_)           // 37376
#define PART  (QA + H1_)                // 37456  (GEMM2 partials / ui partials)
#define WGT   (PART + 10*T_)            // 39456
#define RED   (WGT + T_)                // 39656
#define CSUM  (RED + 16)                // 39672
#define PA1   (CSUM + C_)               // 39736
#define PB2   (PA1 + H1_)
#define PA2   (PB2 + H2_)
#define PWF   (PA2 + H2_)
#define QS    (PWF + H2_)               // 39936
#define CATE  (QS + D_)                 // 40000 (ints)
#define SMEM_FLOATS (CATE + T_)         // 40200
#define SMEM_BYTES (SMEM_FLOATS * 4)

__global__ __launch_bounds__(TPB, 1)
void din_kernel(const float* __restrict__ q, const float* __restrict__ k,
                const int* __restrict__ mask, const int* __restrict__ cate,
                const float* __restrict__ W1, const float* __restrict__ b1,
                const float* __restrict__ a1, const float* __restrict__ W2,
                const float* __restrict__ b2, const float* __restrict__ a2,
                const float* __restrict__ Wf, const float* __restrict__ bf,
                float* __restrict__ out_ui, float* __restrict__ out_ch)
{
    extern __shared__ float sm[];
    int* smi = (int*)sm;
    const int b = blockIdx.x;
    const int tid = threadIdx.x;

    // ---------------- Phase 0: cooperative loads ----------------
    if (tid < D_)  sm[QS + tid]  = q[b * D_ + tid];
    if (tid < H1_) sm[PA1 + tid] = a1[tid];
    if (tid < H2_) { sm[PB2 + tid] = b2[tid]; sm[PA2 + tid] = a2[tid]; sm[PWF + tid] = Wf[tid]; }
    for (int i = tid; i < T_; i += TPB) smi[CATE + i] = cate[b * T_ + i];
    for (int i = tid; i < H1_ * H2_; i += TPB) sm[W2S + i] = W2[i];
    for (int i = tid; i < T_ * D_; i += TPB) {
        int t = i >> 6, d = i & 63;
        sm[KST + d * KSTRIDE + t] = k[(size_t)b * T_ * D_ + i];
    }
    __syncthreads();

    // ---------------- Phase 1: per-batch folded weight M and qa ----------------
    // info@W1 = qa + k_t @ M  with M = W1b - W1c + diag(q) W1d, qa = q@(W1a+W1c)+b1
    for (int e = tid; e < D_ * H1_; e += TPB) {
        int d = e / H1_, h = e - d * H1_;
        sm[MW + e] = W1[(64 + d) * H1_ + h] - W1[(128 + d) * H1_ + h]
                   + sm[QS + d] * W1[(192 + d) * H1_ + h];
    }
    if (tid < H1_) {
        float s = b1[tid];
#pragma unroll 8
        for (int d = 0; d < D_; ++d)
            s += sm[QS + d] * (W1[d * H1_ + tid] + W1[(128 + d) * H1_ + tid]);
        sm[QA + tid] = s;
    }
    __syncthreads();

    // ---------------- Phase 2: GEMM1 [200,64]@[64,80] + PReLU -> h1T ----------------
    if (tid < 250) {
        const int tt = tid / 10, hh = tid - tt * 10;
        const int t0 = tt * 8, h0 = hh * 8;
        float acc[8][8];
#pragma unroll
        for (int i = 0; i < 8; ++i)
#pragma unroll
            for (int j = 0; j < 8; ++j) acc[i][j] = 0.f;

#pragma unroll 4
        for (int d = 0; d < D_; ++d) {
            const float4 kA = *(const float4*)&sm[KST + d * KSTRIDE + t0];
            const float4 kB = *(const float4*)&sm[KST + d * KSTRIDE + t0 + 4];
            const float4 mA = *(const float4*)&sm[MW + d * H1_ + h0];
            const float4 mB = *(const float4*)&sm[MW + d * H1_ + h0 + 4];
            float kv[8] = {kA.x, kA.y, kA.z, kA.w, kB.x, kB.y, kB.z, kB.w};
            float mv[8] = {mA.x, mA.y, mA.z, mA.w, mB.x, mB.y, mB.z, mB.w};
#pragma unroll
            for (int i = 0; i < 8; ++i)
#pragma unroll
                for (int j = 0; j < 8; ++j) acc[i][j] += kv[i] * mv[j];
        }
#pragma unroll
        for (int j = 0; j < 8; ++j) {
            const float bias = sm[QA + h0 + j];
            const float al   = sm[PA1 + h0 + j];
            float o[8];
#pragma unroll
            for (int i = 0; i < 8; ++i) {
                float v = acc[i][j] + bias;
                o[i] = (v > 0.f) ? v : al * v;
            }
            *(float4*)&sm[H1T + (h0 + j) * T_ + t0]     = make_float4(o[0], o[1], o[2], o[3]);
            *(float4*)&sm[H1T + (h0 + j) * T_ + t0 + 4] = make_float4(o[4], o[5], o[6], o[7]);
        }
    }
    __syncthreads();

    // ---------------- Phase 3: GEMM2 [200,80]@[80,40] + PReLU + Wf dot ----------------
    if (tid < 250) {
        const int tt = tid / 10, g = tid - tt * 10;
        const int t0 = tt * 8, j0 = g * 4;
        float acc[8][4];
#pragma unroll
        for (int i = 0; i < 8; ++i)
#pragma unroll
            for (int j = 0; j < 4; ++j) acc[i][j] = 0.f;

#pragma unroll 4
        for (int dd = 0; dd < H1_; ++dd) {
            const float4 lA = *(const float4*)&sm[H1T + dd * T_ + t0];
            const float4 lB = *(const float4*)&sm[H1T + dd * T_ + t0 + 4];
            const float4 wA = *(const float4*)&sm[W2S + dd * H2_ + j0];
            float lv[8] = {lA.x, lA.y, lA.z, lA.w, lB.x, lB.y, lB.z, lB.w};
            float wv[4] = {wA.x, wA.y, wA.z, wA.w};
#pragma unroll
            for (int i = 0; i < 8; ++i)
#pragma unroll
                for (int j = 0; j < 4; ++j) acc[i][j] += lv[i] * wv[j];
        }
        float pl[8] = {0.f, 0.f, 0.f, 0.f, 0.f, 0.f, 0.f, 0.f};
#pragma unroll
        for (int j = 0; j < 4; ++j) {
            const float bb = sm[PB2 + j0 + j];
            const float al = sm[PA2 + j0 + j];
            const float wf = sm[PWF + j0 + j];
#pragma unroll
            for (int i = 0; i < 8; ++i) {
                float v = acc[i][j] + bb;
                v = (v > 0.f) ? v : al * v;
                pl[i] += v * wf;
            }
        }
        *(float4*)&sm[PART + g * T_ + t0]     = make_float4(pl[0], pl[1], pl[2], pl[3]);
        *(float4*)&sm[PART + g * T_ + t0 + 4] = make_float4(pl[4], pl[5], pl[6], pl[7]);
    }
    __syncthreads();

    // ---------------- Phase 4: logits + mask ----------------
    if (tid < T_) {
        float s = bf[0];
#pragma unroll
        for (int g = 0; g < 10; ++g) s += sm[PART + g * T_ + tid];
        if (mask[b * T_ + tid] == 0) s = -4294967295.0f;  // -2^32 + 1
        sm[WGT + tid] = s * 0.125f;                        // / sqrt(64)
    }
    __syncthreads();

    // ---------------- Phase 5: softmax over 200 ----------------
    {
        const int lane = tid & 31, warp = tid >> 5;
        float v = (tid < T_) ? sm[WGT + tid] : -3.4e38f;
#pragma unroll
        for (int o = 16; o; o >>= 1) v = fmaxf(v, __shfl_xor_sync(0xffffffffu, v, o));
        if (lane == 0) sm[RED + warp] = v;
        __syncthreads();
        float mx = sm[RED + 0];
#pragma unroll
        for (int i = 1; i < 8; ++i) mx = fmaxf(mx, sm[RED + i]);
        float e = (tid < T_) ? __expf(sm[WGT + tid] - mx) : 0.f;
        float sv = e;
#pragma unroll
        for (int o = 16; o; o >>= 1) sv += __shfl_xor_sync(0xffffffffu, sv, o);
        if (lane == 0) sm[RED + 8 + warp] = sv;
        __syncthreads();
        float S = 0.f;
#pragma unroll
        for (int i = 0; i < 8; ++i) S += sm[RED + 8 + i];
        if (tid < T_) sm[WGT + tid] = e / S;
    }
    __syncthreads();

    // ---------------- Phase 6: user_interest partials + zero cate acc ----------------
    {
        const int d = tid & 63, g = tid >> 6;
        float s = 0.f;
        const int tb = g * 50;
#pragma unroll 5
        for (int t = tb; t < tb + 50; ++t) s += sm[WGT + t] * sm[KST + d * KSTRIDE + t];
        sm[PART + tid] = s;
    }
    for (int i = tid; i < C_ * D_; i += TPB) sm[MW + i] = 0.f;
    if (tid < C_) sm[CSUM + tid] = 0.f;
    __syncthreads();

    if (tid < D_)
        out_ui[b * D_ + tid] = sm[PART + tid] + sm[PART + 64 + tid]
                             + sm[PART + 128 + tid] + sm[PART + 192 + tid];

    // ---------------- Phase 7: per-category pooling ----------------
    {
        const int d = tid & 63, g = tid >> 6;
        for (int t = g; t < T_; t += 4) {
            const int c = smi[CATE + t];
            const float wv = sm[WGT + t];
            atomicAdd(&sm[MW + c * D_ + d], wv * sm[KST + d * KSTRIDE + t]);
            if (d == 0) atomicAdd(&sm[CSUM + c], wv);
        }
    }
    __syncthreads();

    float* ch = out_ch + (size_t)b * C_ * D_;
    for (int i = tid; i < C_ * D_; i += TPB) {
        const int c = i >> 6;
        ch[i] = sm[MW + i] / (sm[CSUM + c] + 1e-10f);
    }
}

extern "C" void kernel_launch(void* const* d_in, const int* in_sizes, int n_in,
                              void* d_out, int out_size)
{
    const float* q    = (const float*)d_in[0];
    const float* k    = (const float*)d_in[1];
    const int*   mask = (const int*)d_in[2];
    const int*   cate = (const int*)d_in[3];
    // d_in[4] = cate_count (compile-time C_=64)
    const float* W1 = (const float*)d_in[5];
    const float* b1 = (const float*)d_in[6];
    const float* a1 = (const float*)d_in[7];
    const float* W2 = (const float*)d_in[8];
    const float* b2 = (const float*)d_in[9];
    const float* a2 = (const float*)d_in[10];
    const float* Wf = (const float*)d_in[11];
    const float* bf = (const float*)d_in[12];

    const int B = in_sizes[0] / D_;
    float* out_ui = (float*)d_out;                     // [B, 64]
    float* out_ch = (float*)d_out + (size_t)B * D_;    // [B, 64, 64]

    cudaFuncSetAttribute(din_kernel, cudaFuncAttributeMaxDynamicSharedMemorySize, SMEM_BYTES);
    din_kernel<<<B, TPB, SMEM_BYTES>>>(q, k, mask, cate, W1, b1, a1, W2, b2, a2, Wf, bf,
                                       out_ui, out_ch);
}

// round 2
// speedup vs baseline: 1.1889x; 1.1889x over previous
#include <cuda_runtime.h>

#define TPB 512
#define T_ 200
#define D_ 64
#define H1_ 80
#define H2_ 40
#define C_ 64
#define KSTRIDE 204

// shared-memory float offsets
#define KST   0                          // 64 x 204
#define H1T   (KST + D_*KSTRIDE)         // 13056: 80 x 200 (h-major)
#define MW    (H1T + H1_*T_)             // 29056: folded M [64][80]
#define W2S   (MW + D_*H1_)              // 34176: W2 [80][40]
#define QA    (W2S + H1_*H2_)            // 37376: per-batch bias [80]
#define PART  (QA + H1_)                 // 37456: 10 x 200 partials / ui partials
#define WGT   (PART + 10*T_)             // 39456: softmax weights [200]
#define RED   (WGT + T_)                 // 39656: [32] reduction scratch
#define PA1   (RED + 32)                 // 39688
#define PB2   (PA1 + H1_)                // 39768
#define PA2   (PB2 + H2_)                // 39808
#define PWF   (PA2 + H2_)                // 39848
#define QS    (PWF + H2_)                // 39888
#define CATE  (QS + D_)                  // 39952 (int)
#define CNT   (CATE + T_)                // 40152 (int) bucket counts
#define CNT2  (CNT + C_)                 // 40216 (int) scatter cursors
#define BST   (CNT2 + C_)                // 40280 (int) bucket starts
#define TLIST (BST + C_)                 // 40344 (int) sorted t indices
#define SMEM_FLOATS (TLIST + T_)         // 40544
#define SMEM_BYTES (SMEM_FLOATS * 4)

typedef unsigned long long ull;

__device__ __forceinline__ ull ffma2(ull a, ull b, ull c) {
    ull d;
    asm("fma.rn.f32x2 %0, %1, %2, %3;" : "=l"(d) : "l"(a), "l"(b), "l"(c));
    return d;
}
__device__ __forceinline__ ull dup2(float x) {
    ull r;
    asm("mov.b64 %0, {%1, %1};" : "=l"(r) : "f"(x));
    return r;
}
__device__ __forceinline__ float2 unpk(ull v) {
    float2 f;
    asm("mov.b64 {%0, %1}, %2;" : "=f"(f.x), "=f"(f.y) : "l"(v));
    return f;
}

__global__ __launch_bounds__(TPB, 1)
void din_kernel(const float* __restrict__ q, const float* __restrict__ k,
                const int* __restrict__ mask, const int* __restrict__ cate,
                const float* __restrict__ W1, const float* __restrict__ b1,
                const float* __restrict__ a1, const float* __restrict__ W2,
                const float* __restrict__ b2, const float* __restrict__ a2,
                const float* __restrict__ Wf, const float* __restrict__ bf,
                float* __restrict__ out_ui, float* __restrict__ out_ch)
{
    extern __shared__ float sm[];
    int* smi = (int*)sm;
    const int b = blockIdx.x;
    const int tid = threadIdx.x;

    // ---------------- Phase 0: cooperative loads ----------------
    if (tid < D_)  sm[QS + tid]  = q[b * D_ + tid];
    if (tid < H1_) sm[PA1 + tid] = a1[tid];
    if (tid < H2_) { sm[PB2 + tid] = b2[tid]; sm[PA2 + tid] = a2[tid]; sm[PWF + tid] = Wf[tid]; }
    if (tid < T_)  smi[CATE + tid] = cate[b * T_ + tid];
    if (tid < C_)  smi[CNT + tid] = 0;
    for (int i = tid; i < H1_ * H2_; i += TPB) sm[W2S + i] = W2[i];
    // k transpose: [200,64] row-major -> ksT [64][204]
    {
        const float4* k4 = (const float4*)(k + (size_t)b * T_ * D_);
        for (int idx = tid; idx < T_ * 16; idx += TPB) {
            float4 v = k4[idx];
            int t = idx >> 4, d0 = (idx & 15) << 2;
            sm[KST + (d0    ) * KSTRIDE + t] = v.x;
            sm[KST + (d0 + 1) * KSTRIDE + t] = v.y;
            sm[KST + (d0 + 2) * KSTRIDE + t] = v.z;
            sm[KST + (d0 + 3) * KSTRIDE + t] = v.w;
        }
    }
    __syncthreads();

    // ---------------- Phase 1: folded weight M, qa bias, bucket counts ----------------
    // info@W1 = qa + k_t @ M,  M = W1b - W1c + diag(q) W1d,  qa = q@(W1a+W1c)+b1
    for (int e = tid; e < D_ * H1_; e += TPB) {
        int d = e / H1_, h = e - d * H1_;
        sm[MW + e] = W1[(64 + d) * H1_ + h] - W1[(128 + d) * H1_ + h]
                   + sm[QS + d] * W1[(192 + d) * H1_ + h];
    }
    if (tid < H1_) {
        float s = b1[tid];
#pragma unroll 8
        for (int d = 0; d < D_; ++d)
            s += sm[QS + d] * (W1[d * H1_ + tid] + W1[(128 + d) * H1_ + tid]);
        sm[QA + tid] = s;
    }
    if (tid < T_) atomicAdd(&smi[CNT + smi[CATE + tid]], 1);
    __syncthreads();

    // ---------------- Phase 2: GEMM1 [200,64]@[64,80] + PReLU -> H1T (f32x2) ----------
    if (tid < 500) {
        const int tt = tid / 10, hh = tid - tt * 10;
        const int t0 = tt * 4, h0 = hh * 8;
        ull acc[4][4];   // [t][h-pair]
#pragma unroll
        for (int i = 0; i < 4; ++i)
#pragma unroll
            for (int j = 0; j < 4; ++j) acc[i][j] = 0ull;

#pragma unroll 4
        for (int d = 0; d < D_; ++d) {
            const float4 kA = *(const float4*)&sm[KST + d * KSTRIDE + t0];
            const ulonglong2 mA = *(const ulonglong2*)&sm[MW + d * H1_ + h0];
            const ulonglong2 mB = *(const ulonglong2*)&sm[MW + d * H1_ + h0 + 4];
            ull kd[4] = {dup2(kA.x), dup2(kA.y), dup2(kA.z), dup2(kA.w)};
            ull mp[4] = {mA.x, mA.y, mB.x, mB.y};
#pragma unroll
            for (int i = 0; i < 4; ++i)
#pragma unroll
                for (int j = 0; j < 4; ++j) acc[i][j] = ffma2(kd[i], mp[j], acc[i][j]);
        }
        float av[4][8];
#pragma unroll
        for (int i = 0; i < 4; ++i)
#pragma unroll
            for (int j = 0; j < 4; ++j) {
                float2 p = unpk(acc[i][j]);
                av[i][2 * j] = p.x; av[i][2 * j + 1] = p.y;
            }
#pragma unroll
        for (int j = 0; j < 8; ++j) {
            const float bias = sm[QA + h0 + j];
            const float al   = sm[PA1 + h0 + j];
            float o[4];
#pragma unroll
            for (int i = 0; i < 4; ++i) {
                float v = av[i][j] + bias;
                o[i] = (v > 0.f) ? v : al * v;
            }
            *(float4*)&sm[H1T + (h0 + j) * T_ + t0] = make_float4(o[0], o[1], o[2], o[3]);
        }
    }
    __syncthreads();

    // ---------------- Phase 3: GEMM2 [200,80]@[80,40] + PReLU + Wf dot (f32x2) --------
    if (tid < 500) {
        const int tt = tid / 10, hh = tid - tt * 10;
        const int t0 = tt * 4, j0 = hh * 4;
        ull acc2[2][4];  // [t-pair][h]
#pragma unroll
        for (int p = 0; p < 2; ++p)
#pragma unroll
            for (int j = 0; j < 4; ++j) acc2[p][j] = 0ull;

#pragma unroll 4
        for (int dd = 0; dd < H1_; ++dd) {
            const ulonglong2 lp = *(const ulonglong2*)&sm[H1T + dd * T_ + t0];
            const float4 wv = *(const float4*)&sm[W2S + dd * H2_ + j0];
            ull wd[4] = {dup2(wv.x), dup2(wv.y), dup2(wv.z), dup2(wv.w)};
            ull lv[2] = {lp.x, lp.y};
#pragma unroll
            for (int p = 0; p < 2; ++p)
#pragma unroll
                for (int j = 0; j < 4; ++j) acc2[p][j] = ffma2(lv[p], wd[j], acc2[p][j]);
        }
        float pl[4] = {0.f, 0.f, 0.f, 0.f};
#pragma unroll
        for (int j = 0; j < 4; ++j) {
            const float bb = sm[PB2 + j0 + j];
            const float al = sm[PA2 + j0 + j];
            const float wf = sm[PWF + j0 + j];
            float2 v0 = unpk(acc2[0][j]);
            float2 v1 = unpk(acc2[1][j]);
            float v[4] = {v0.x, v0.y, v1.x, v1.y};
#pragma unroll
            for (int i = 0; i < 4; ++i) {
                float x = v[i] + bb;
                x = (x > 0.f) ? x : al * x;
                pl[i] += x * wf;
            }
        }
        *(float4*)&sm[PART + hh * T_ + t0] = make_float4(pl[0], pl[1], pl[2], pl[3]);
    }
    __syncthreads();

    // ---------------- Phase 4: logits + mask; warp15: bucket prefix scan -------------
    if (tid < T_) {
        float s = bf[0];
#pragma unroll
        for (int g = 0; g < 10; ++g) s += sm[PART + g * T_ + tid];
        if (mask[b * T_ + tid] == 0) s = -4294967295.0f;   // -2^32 + 1
        sm[WGT + tid] = s * 0.125f;                         // / sqrt(64)
    }
    if (tid >= 480) {
        const int l = tid - 480;
        const int c0 = smi[CNT + 2 * l], c1 = smi[CNT + 2 * l + 1];
        int s = c0 + c1;
#pragma unroll
        for (int off = 1; off < 32; off <<= 1) {
            int n = __shfl_up_sync(0xffffffffu, s, off);
            if (l >= off) s += n;
        }
        const int excl = s - (c0 + c1);
        smi[BST + 2 * l] = excl;        smi[BST + 2 * l + 1] = excl + c0;
        smi[CNT2 + 2 * l] = excl;       smi[CNT2 + 2 * l + 1] = excl + c0;
    }
    __syncthreads();

    // ---------------- Phase 5: softmax over 200 ----------------
    {
        const int lane = tid & 31, warp = tid >> 5;
        float v = (tid < T_) ? sm[WGT + tid] : -3.4e38f;
#pragma unroll
        for (int o = 16; o; o >>= 1) v = fmaxf(v, __shfl_xor_sync(0xffffffffu, v, o));
        if (lane == 0) sm[RED + warp] = v;
        __syncthreads();
        float mx = sm[RED + 0];
#pragma unroll
        for (int i = 1; i < 16; ++i) mx = fmaxf(mx, sm[RED + i]);
        float e = (tid < T_) ? __expf(sm[WGT + tid] - mx) : 0.f;
        float sv = e;
#pragma unroll
        for (int o = 16; o; o >>= 1) sv += __shfl_xor_sync(0xffffffffu, sv, o);
        if (lane == 0) sm[RED + 16 + warp] = sv;
        __syncthreads();
        float S = 0.f;
#pragma unroll
        for (int i = 0; i < 16; ++i) S += sm[RED + 16 + i];
        if (tid < T_) sm[WGT + tid] = e / S;
    }
    __syncthreads();

    // ---------------- Phase 5b+6: bucket scatter + user_interest partials ------------
    if (tid < T_) {
        const int c = smi[CATE + tid];
        const int pos = atomicAdd(&smi[CNT2 + c], 1);
        smi[TLIST + pos] = tid;
    }
    {
        const int d = tid & 63, g = tid >> 6;   // 8 groups x 25 t
        float s = 0.f;
        const int tb = g * 25;
#pragma unroll 5
        for (int t = tb; t < tb + 25; ++t) s += sm[WGT + t] * sm[KST + d * KSTRIDE + t];
        sm[PART + tid] = s;
    }
    __syncthreads();

    if (tid < D_) {
        float s = 0.f;
#pragma unroll
        for (int g = 0; g < 8; ++g) s += sm[PART + g * 64 + tid];
        out_ui[b * D_ + tid] = s;
    }

    // ---------------- Phase 7: bucketed per-category pooling (no atomics) ------------
    {
        const int g = tid >> 6, d = tid & 63;   // 8 groups of 64 lanes; 8 cats each
        float* ch = out_ch + (size_t)b * C_ * D_;
        for (int c = g; c < C_; c += 8) {
            const int len = smi[CNT + c];
            const int st  = smi[BST + c];
            float acc = 0.f, ws = 0.f;
            for (int i = 0; i < len; ++i) {
                const int t = smi[TLIST + st + i];
                const float w = sm[WGT + t];
                ws  += w;
                acc += w * sm[KST + d * KSTRIDE + t];
            }
            ch[c * D_ + d] = acc / (ws + 1e-10f);
        }
    }
}

extern "C" void kernel_launch(void* const* d_in, const int* in_sizes, int n_in,
                              void* d_out, int out_size)
{
    const float* q    = (const float*)d_in[0];
    const float* k    = (const float*)d_in[1];
    const int*   mask = (const int*)d_in[2];
    const int*   cate = (const int*)d_in[3];
    // d_in[4] = cate_count (compile-time C_=64)
    const float* W1 = (const float*)d_in[5];
    const float* b1 = (const float*)d_in[6];
    const float* a1 = (const float*)d_in[7];
    const float* W2 = (const float*)d_in[8];
    const float* b2 = (const float*)d_in[9];
    const float* a2 = (const float*)d_in[10];
    const float* Wf = (const float*)d_in[11];
    const float* bf = (const float*)d_in[12];

    const int B = in_sizes[0] / D_;
    float* out_ui = (float*)d_out;                     // [B, 64]
    float* out_ch = (float*)d_out + (size_t)B * D_;    // [B, 64, 64]

    cudaFuncSetAttribute(din_kernel, cudaFuncAttributeMaxDynamicSharedMemorySize, SMEM_BYTES);
    din_kernel<<<B, TPB, SMEM_BYTES>>>(q, k, mask, cate, W1, b1, a1, W2, b2, a2, Wf, bf,
                                       out_ui, out_ch);
}

// round 3
// speedup vs baseline: 1.5848x; 1.3330x over previous
#include <cuda_runtime.h>
#include <cuda_fp16.h>

#define TPB 512
#define T_ 200
#define D_ 64
#define H1_ 80
#define H2_ 40
#define C_ 64
#define KSTRIDE 204
#define H1S2 104                 // H1T row stride in half2 units

// float-index offsets into dynamic smem
#define KST   0                  // [64][204] f32             (52224 B)
#define H1T_H2 13056             // half2-index: [80][104] h2 (33280 B @ byte 52224)
#define MW    21376              // [64][80] f32 folded M     (20480 B @ byte 85504)
#define PART  21376              // alias MW: [10][200] f32 partials / [512] ui partials
#define QA    26496              // [80]
#define WGT   26576              // [200]
#define RED   26776              // [32]
#define PA1   26808              // [80]
#define PB2   26888              // [40]
#define PA2   26928              // [40]
#define PWF   26968              // [40]
#define QS    27008              // [64]
#define CATE  27072              // [200] int
#define CNT   27272              // [64] int
#define CNT2  27336              // [64] int
#define BST   27400              // [64] int
#define TLIST 27464              // [200] int
#define SMEM_FLOATS 27664
#define SMEM_BYTES (SMEM_FLOATS * 4)   // 110656 B -> 2 CTAs/SM

typedef unsigned long long ull;

__device__ __forceinline__ ull ffma2(ull a, ull b, ull c) {
    ull d;
    asm("fma.rn.f32x2 %0, %1, %2, %3;" : "=l"(d) : "l"(a), "l"(b), "l"(c));
    return d;
}
__device__ __forceinline__ ull dup2(float x) {
    ull r;
    asm("mov.b64 %0, {%1, %1};" : "=l"(r) : "f"(x));
    return r;
}
__device__ __forceinline__ float2 unpk(ull v) {
    float2 f;
    asm("mov.b64 {%0, %1}, %2;" : "=f"(f.x), "=f"(f.y) : "l"(v));
    return f;
}

__global__ __launch_bounds__(TPB, 2)
void din_kernel(const float* __restrict__ q, const float* __restrict__ k,
                const int* __restrict__ mask, const int* __restrict__ cate,
                const float* __restrict__ W1, const float* __restrict__ b1,
                const float* __restrict__ a1, const float* __restrict__ W2,
                const float* __restrict__ b2, const float* __restrict__ a2,
                const float* __restrict__ Wf, const float* __restrict__ bf,
                float* __restrict__ out_ui, float* __restrict__ out_ch)
{
    extern __shared__ float sm[];
    int* smi = (int*)sm;
    __half2* h1s = (__half2*)sm + H1T_H2;
    const int b = blockIdx.x;
    const int tid = threadIdx.x;

    // ---------------- Phase 0: cooperative loads ----------------
    if (tid < D_)  sm[QS + tid]  = q[b * D_ + tid];
    if (tid < H1_) sm[PA1 + tid] = a1[tid];
    if (tid < H2_) { sm[PB2 + tid] = b2[tid]; sm[PA2 + tid] = a2[tid]; sm[PWF + tid] = Wf[tid]; }
    if (tid < T_)  smi[CATE + tid] = cate[b * T_ + tid];
    if (tid < C_)  smi[CNT + tid] = 0;
    // k transpose: [200,64] row-major -> ksT [64][204]
    {
        const float4* k4 = (const float4*)(k + (size_t)b * T_ * D_);
        for (int idx = tid; idx < T_ * 16; idx += TPB) {
            float4 v = k4[idx];
            int t = idx >> 4, d0 = (idx & 15) << 2;
            sm[KST + (d0    ) * KSTRIDE + t] = v.x;
            sm[KST + (d0 + 1) * KSTRIDE + t] = v.y;
            sm[KST + (d0 + 2) * KSTRIDE + t] = v.z;
            sm[KST + (d0 + 3) * KSTRIDE + t] = v.w;
        }
    }
    __syncthreads();

    // ---------------- Phase 1: folded weight M, qa bias, bucket counts ----------------
    // info@W1 = qa + k_t @ M,  M = W1b - W1c + diag(q) W1d,  qa = q@(W1a+W1c)+b1
    for (int e = tid; e < D_ * H1_; e += TPB) {
        int d = e / H1_, h = e - d * H1_;
        sm[MW + e] = W1[(64 + d) * H1_ + h] - W1[(128 + d) * H1_ + h]
                   + sm[QS + d] * W1[(192 + d) * H1_ + h];
    }
    if (tid < 320) {
        const int h = tid >> 2, qq = tid & 3;
        float s = 0.f;
        const int d0 = qq * 16;
#pragma unroll 4
        for (int d = d0; d < d0 + 16; ++d)
            s += sm[QS + d] * (W1[d * H1_ + h] + W1[(128 + d) * H1_ + h]);
        s += __shfl_xor_sync(0xffffffffu, s, 1);
        s += __shfl_xor_sync(0xffffffffu, s, 2);
        if (qq == 0) sm[QA + h] = s + b1[h];
    }
    if (tid < T_) atomicAdd(&smi[CNT + smi[CATE + tid]], 1);
    __syncthreads();

    // ---------------- Phase 2: GEMM1 [200,64]@[64,80] + PReLU -> H1T fp16 -------------
    if (tid < 500) {
        const int tt = tid / 10, hh = tid - tt * 10;
        const int t0 = tt * 4, h0 = hh * 8;
        ull acc[4][4];   // [t][h-pair]
#pragma unroll
        for (int i = 0; i < 4; ++i)
#pragma unroll
            for (int j = 0; j < 4; ++j) acc[i][j] = 0ull;

#pragma unroll 4
        for (int d = 0; d < D_; ++d) {
            const float4 kA = *(const float4*)&sm[KST + d * KSTRIDE + t0];
            const ulonglong2 mA = *(const ulonglong2*)&sm[MW + d * H1_ + h0];
            const ulonglong2 mB = *(const ulonglong2*)&sm[MW + d * H1_ + h0 + 4];
            ull kd[4] = {dup2(kA.x), dup2(kA.y), dup2(kA.z), dup2(kA.w)};
            ull mp[4] = {mA.x, mA.y, mB.x, mB.y};
#pragma unroll
            for (int i = 0; i < 4; ++i)
#pragma unroll
                for (int j = 0; j < 4; ++j) acc[i][j] = ffma2(kd[i], mp[j], acc[i][j]);
        }
#pragma unroll
        for (int j = 0; j < 4; ++j) {          // h-pairs
#pragma unroll
            for (int p = 0; p < 2; ++p) {       // element within pair
                const int h = h0 + 2 * j + p;
                const float bias = sm[QA + h];
                const float al   = sm[PA1 + h];
                float o[4];
#pragma unroll
                for (int i = 0; i < 4; ++i) {
                    float2 v2 = unpk(acc[i][j]);
                    float v = (p == 0 ? v2.x : v2.y) + bias;
                    o[i] = (v > 0.f) ? v : al * v;
                }
                __half2 q01 = __float22half2_rn(make_float2(o[0], o[1]));
                __half2 q23 = __float22half2_rn(make_float2(o[2], o[3]));
                __half2* dst = &h1s[h * H1S2 + (t0 >> 1)];
                *(uint2*)dst = make_uint2(*(unsigned*)&q01, *(unsigned*)&q23);
            }
        }
    }
    __syncthreads();

    // ---------------- Phase 3: GEMM2 [200,80]@[80,40] + PReLU + Wf dot ----------------
    if (tid < 500) {
        const int tt = tid / 10, hh = tid - tt * 10;
        const int t0 = tt * 4, j0 = hh * 4;
        ull acc2[4][2];  // [t][j-pair]
#pragma unroll
        for (int i = 0; i < 4; ++i) { acc2[i][0] = 0ull; acc2[i][1] = 0ull; }

#pragma unroll 4
        for (int dd = 0; dd < H1_; ++dd) {
            const uint2 hp = *(const uint2*)&h1s[dd * H1S2 + (t0 >> 1)];
            const ulonglong2 wv = *(const ulonglong2*)&W2[dd * H2_ + j0]; // L1-resident
            float2 f0 = __half22float2(*(__half2*)&hp.x);
            float2 f1 = __half22float2(*(__half2*)&hp.y);
            ull td[4] = {dup2(f0.x), dup2(f0.y), dup2(f1.x), dup2(f1.y)};
#pragma unroll
            for (int i = 0; i < 4; ++i) {
                acc2[i][0] = ffma2(td[i], wv.x, acc2[i][0]);
                acc2[i][1] = ffma2(td[i], wv.y, acc2[i][1]);
            }
        }
        float pl[4] = {0.f, 0.f, 0.f, 0.f};
#pragma unroll
        for (int jp = 0; jp < 2; ++jp) {
#pragma unroll
            for (int p = 0; p < 2; ++p) {
                const int j = j0 + 2 * jp + p;
                const float bb = sm[PB2 + j];
                const float al = sm[PA2 + j];
                const float wf = sm[PWF + j];
#pragma unroll
                for (int i = 0; i < 4; ++i) {
                    float2 v2 = unpk(acc2[i][jp]);
                    float x = (p == 0 ? v2.x : v2.y) + bb;
                    x = (x > 0.f) ? x : al * x;
                    pl[i] += x * wf;
                }
            }
        }
        *(float4*)&sm[PART + hh * T_ + t0] = make_float4(pl[0], pl[1], pl[2], pl[3]);
    }
    __syncthreads();

    // ---------------- Phase 4: logits + mask; warp15: bucket prefix scan -------------
    if (tid < T_) {
        float s = bf[0];
#pragma unroll
        for (int g = 0; g < 10; ++g) s += sm[PART + g * T_ + tid];
        if (mask[b * T_ + tid] == 0) s = -4294967295.0f;   // -2^32 + 1
        sm[WGT + tid] = s * 0.125f;                         // / sqrt(64)
    }
    if (tid >= 480) {
        const int l = tid - 480;
        const int c0 = smi[CNT + 2 * l], c1 = smi[CNT + 2 * l + 1];
        int s = c0 + c1;
#pragma unroll
        for (int off = 1; off < 32; off <<= 1) {
            int n = __shfl_up_sync(0xffffffffu, s, off);
            if (l >= off) s += n;
        }
        const int excl = s - (c0 + c1);
        smi[BST + 2 * l] = excl;        smi[BST + 2 * l + 1] = excl + c0;
        smi[CNT2 + 2 * l] = excl;       smi[CNT2 + 2 * l + 1] = excl + c0;
    }
    __syncthreads();

    // ---------------- Phase 5: softmax over 200 ----------------
    {
        const int lane = tid & 31, warp = tid >> 5;
        float v = (tid < T_) ? sm[WGT + tid] : -3.4e38f;
#pragma unroll
        for (int o = 16; o; o >>= 1) v = fmaxf(v, __shfl_xor_sync(0xffffffffu, v, o));
        if (lane == 0) sm[RED + warp] = v;
        __syncthreads();
        float mx = sm[RED + 0];
#pragma unroll
        for (int i = 1; i < 16; ++i) mx = fmaxf(mx, sm[RED + i]);
        float e = (tid < T_) ? __expf(sm[WGT + tid] - mx) : 0.f;
        float sv = e;
#pragma unroll
        for (int o = 16; o; o >>= 1) sv += __shfl_xor_sync(0xffffffffu, sv, o);
        if (lane == 0) sm[RED + 16 + warp] = sv;
        __syncthreads();
        float S = 0.f;
#pragma unroll
        for (int i = 0; i < 16; ++i) S += sm[RED + 16 + i];
        if (tid < T_) sm[WGT + tid] = e / S;
    }
    __syncthreads();

    // ---------------- Phase 5b+6: bucket scatter + user_interest partials ------------
    if (tid < T_) {
        const int c = smi[CATE + tid];
        const int pos = atomicAdd(&smi[CNT2 + c], 1);
        smi[TLIST + pos] = tid;
    }
    {
        const int d = tid & 63, g = tid >> 6;   // 8 groups x 25 t
        float s = 0.f;
        const int tb = g * 25;
#pragma unroll 5
        for (int t = tb; t < tb + 25; ++t) s += sm[WGT + t] * sm[KST + d * KSTRIDE + t];
        sm[PART + tid] = s;
    }
    __syncthreads();

    if (tid < D_) {
        float s = 0.f;
#pragma unroll
        for (int g = 0; g < 8; ++g) s += sm[PART + g * 64 + tid];
        out_ui[b * D_ + tid] = s;
    }

    // ---------------- Phase 7: bucketed per-category pooling (no atomics) ------------
    {
        const int g = tid >> 6, d = tid & 63;   // 8 groups of 64 lanes; 8 cats each
        float* ch = out_ch + (size_t)b * C_ * D_;
        for (int c = g; c < C_; c += 8) {
            const int len = smi[CNT + c];
            const int st  = smi[BST + c];
            float acc = 0.f, ws = 0.f;
            for (int i = 0; i < len; ++i) {
                const int t = smi[TLIST + st + i];
                const float w = sm[WGT + t];
                ws  += w;
                acc += w * sm[KST + d * KSTRIDE + t];
            }
            ch[c * D_ + d] = acc / (ws + 1e-10f);
        }
    }
}

extern "C" void kernel_launch(void* const* d_in, const int* in_sizes, int n_in,
                              void* d_out, int out_size)
{
    const float* q    = (const float*)d_in[0];
    const float* k    = (const float*)d_in[1];
    const int*   mask = (const int*)d_in[2];
    const int*   cate = (const int*)d_in[3];
    // d_in[4] = cate_count (compile-time C_=64)
    const float* W1 = (const float*)d_in[5];
    const float* b1 = (const float*)d_in[6];
    const float* a1 = (const float*)d_in[7];
    const float* W2 = (const float*)d_in[8];
    const float* b2 = (const float*)d_in[9];
    const float* a2 = (const float*)d_in[10];
    const float* Wf = (const float*)d_in[11];
    const float* bf = (const float*)d_in[12];

    const int B = in_sizes[0] / D_;
    float* out_ui = (float*)d_out;                     // [B, 64]
    float* out_ch = (float*)d_out + (size_t)B * D_;    // [B, 64, 64]

    cudaFuncSetAttribute(din_kernel, cudaFuncAttributeMaxDynamicSharedMemorySize, SMEM_BYTES);
    din_kernel<<<B, TPB, SMEM_BYTES>>>(q, k, mask, cate, W1, b1, a1, W2, b2, a2, Wf, bf,
                                       out_ui, out_ch);
}

// round 4
// speedup vs baseline: 2.3200x; 1.4639x over previous
#include <cuda_runtime.h>
#include <cuda_fp16.h>

#define TPB 512
#define T_ 200
#define D_ 64
#define H1_ 80
#define H2_ 40
#define C_ 64
#define KSTRIDE 204
#define H1S2 100                 // h1 row stride in half2 units

// float-index offsets into dynamic smem
#define KST   0                  // [64][204] f32 (52224 B)
#define H1REG 13056              // region: h1 fp16 [80][100 h2] (32000B) / k16 [200][64 h]
#define MW    21056              // [64][80] f32 folded M (20480B), aliased w/ PART
#define PART  21056              // [10][200] f32 partials / [512] ui partials
#define QA    26176              // [80]
#define WGT   26256              // [200]
#define RED   26456              // [32]
#define PA1   26488              // [80]
#define PB2   26568              // [40]
#define PA2   26608              // [40]
#define PWF   26648              // [40]
#define QS    26688              // [64]
#define CATE  26752              // [200] int
#define CNT   26952              // [64] int
#define CNT2  27016              // [64] int
#define BST   27080              // [64] int
#define TLIST 27144              // [200] int
#define SMEM_FLOATS 27344
#define SMEM_BYTES (SMEM_FLOATS * 4)   // 109376 B -> 2 CTAs/SM

typedef unsigned long long ull;

__device__ __forceinline__ ull ffma2(ull a, ull b, ull c) {
    ull d;
    asm("fma.rn.f32x2 %0, %1, %2, %3;" : "=l"(d) : "l"(a), "l"(b), "l"(c));
    return d;
}
__device__ __forceinline__ ull dup2(float x) {
    ull r;
    asm("mov.b64 %0, {%1, %1};" : "=l"(r) : "f"(x));
    return r;
}
__device__ __forceinline__ float2 unpk(ull v) {
    float2 f;
    asm("mov.b64 {%0, %1}, %2;" : "=f"(f.x), "=f"(f.y) : "l"(v));
    return f;
}

__global__ __launch_bounds__(TPB, 2)
void din_kernel(const float* __restrict__ q, const float* __restrict__ k,
                const int* __restrict__ mask, const int* __restrict__ cate,
                const float* __restrict__ W1, const float* __restrict__ b1,
                const float* __restrict__ a1, const float* __restrict__ W2,
                const float* __restrict__ b2, const float* __restrict__ a2,
                const float* __restrict__ Wf, const float* __restrict__ bf,
                float* __restrict__ out_ui, float* __restrict__ out_ch)
{
    extern __shared__ float sm[];
    int* smi = (int*)sm;
    __half2* h1s = (__half2*)sm + H1REG;          // half2 is 4B: same index scale as float
    __half*  k16 = (__half*)((__half2*)sm + H1REG);
    const int b = blockIdx.x;
    const int tid = threadIdx.x;
    const int lane = tid & 31, warp = tid >> 5;

    // ---------------- Phase 0: cooperative loads ----------------
    if (tid < D_)  sm[QS + tid]  = q[b * D_ + tid];
    if (tid < H1_) sm[PA1 + tid] = a1[tid];
    if (tid < H2_) { sm[PB2 + tid] = b2[tid]; sm[PA2 + tid] = a2[tid]; sm[PWF + tid] = Wf[tid]; }
    if (tid < T_)  smi[CATE + tid] = cate[b * T_ + tid];
    if (tid < C_)  smi[CNT + tid] = 0;
    // k transpose, conflict-free STS: warp w owns float4-column w (d0 = 4w)
    {
        const float4* k4 = (const float4*)(k + (size_t)b * T_ * D_);
        const int d0 = warp * 4;
        for (int t = lane; t < T_; t += 32) {
            float4 v = k4[t * 16 + warp];
            sm[KST + (d0    ) * KSTRIDE + t] = v.x;
            sm[KST + (d0 + 1) * KSTRIDE + t] = v.y;
            sm[KST + (d0 + 2) * KSTRIDE + t] = v.z;
            sm[KST + (d0 + 3) * KSTRIDE + t] = v.w;
        }
    }
    __syncthreads();

    // ---------------- Phase 1: folded weight M, qa bias, bucket counts ----------------
    // info@W1 = qa + k_t @ M,  M = W1b - W1c + diag(q) W1d,  qa = q@(W1a+W1c)+b1
    for (int e = tid; e < D_ * H1_; e += TPB) {
        int d = e / H1_, h = e - d * H1_;
        sm[MW + e] = W1[(64 + d) * H1_ + h] - W1[(128 + d) * H1_ + h]
                   + sm[QS + d] * W1[(192 + d) * H1_ + h];
    }
    if (tid < 320) {
        const int h = tid >> 2, qq = tid & 3;
        float s = 0.f;
        const int d0 = qq * 16;
#pragma unroll 4
        for (int d = d0; d < d0 + 16; ++d)
            s += sm[QS + d] * (W1[d * H1_ + h] + W1[(128 + d) * H1_ + h]);
        s += __shfl_xor_sync(0xffffffffu, s, 1);
        s += __shfl_xor_sync(0xffffffffu, s, 2);
        if (qq == 0) sm[QA + h] = s + b1[h];
    }
    if (tid < T_) atomicAdd(&smi[CNT + smi[CATE + tid]], 1);
    __syncthreads();

    // ---------------- Phase 2: GEMM1 [200,64]@[64,80] + PReLU -> h1 fp16 --------------
    // tiling: tt = tid%50 (t0 lane-consecutive), hh = tid/50 (warp-uniform)
    if (tid < 500) {
        const int tt = tid % 50, hh = tid / 50;
        const int t0 = tt * 4, h0 = hh * 8;
        ull acc[4][4];   // [t][h-pair]
#pragma unroll
        for (int i = 0; i < 4; ++i)
#pragma unroll
            for (int j = 0; j < 4; ++j) acc[i][j] = 0ull;

#pragma unroll 4
        for (int d = 0; d < D_; ++d) {
            const float4 kA = *(const float4*)&sm[KST + d * KSTRIDE + t0];
            const ulonglong2 mA = *(const ulonglong2*)&sm[MW + d * H1_ + h0];      // bcast
            const ulonglong2 mB = *(const ulonglong2*)&sm[MW + d * H1_ + h0 + 4];  // bcast
            ull kd[4] = {dup2(kA.x), dup2(kA.y), dup2(kA.z), dup2(kA.w)};
            ull mp[4] = {mA.x, mA.y, mB.x, mB.y};
#pragma unroll
            for (int i = 0; i < 4; ++i)
#pragma unroll
                for (int j = 0; j < 4; ++j) acc[i][j] = ffma2(kd[i], mp[j], acc[i][j]);
        }
#pragma unroll
        for (int j = 0; j < 4; ++j) {          // h-pairs
#pragma unroll
            for (int p = 0; p < 2; ++p) {
                const int h = h0 + 2 * j + p;
                const float bias = sm[QA + h];
                const float al   = sm[PA1 + h];
                float o[4];
#pragma unroll
                for (int i = 0; i < 4; ++i) {
                    float2 v2 = unpk(acc[i][j]);
                    float v = (p == 0 ? v2.x : v2.y) + bias;
                    o[i] = (v > 0.f) ? v : al * v;
                }
                __half2 q01 = __float22half2_rn(make_float2(o[0], o[1]));
                __half2 q23 = __float22half2_rn(make_float2(o[2], o[3]));
                *(uint2*)&h1s[h * H1S2 + (t0 >> 1)] =
                    make_uint2(*(unsigned*)&q01, *(unsigned*)&q23);
            }
        }
    }
    __syncthreads();

    // ---------------- Phase 3: GEMM2 [200,80]@[80,40] + PReLU + Wf dot ----------------
    if (tid < 500) {
        const int tt = tid % 50, hh = tid / 50;
        const int t0 = tt * 4, j0 = hh * 4;
        ull acc2[4][2];  // [t][j-pair]
#pragma unroll
        for (int i = 0; i < 4; ++i) { acc2[i][0] = 0ull; acc2[i][1] = 0ull; }

#pragma unroll 4
        for (int dd = 0; dd < H1_; ++dd) {
            const uint2 hp = *(const uint2*)&h1s[dd * H1S2 + (t0 >> 1)];        // cf LDS
            const ulonglong2 wv = *(const ulonglong2*)&W2[dd * H2_ + j0];       // warp-uniform LDG
            float2 f0 = __half22float2(*(__half2*)&hp.x);
            float2 f1 = __half22float2(*(__half2*)&hp.y);
            ull td[4] = {dup2(f0.x), dup2(f0.y), dup2(f1.x), dup2(f1.y)};
#pragma unroll
            for (int i = 0; i < 4; ++i) {
                acc2[i][0] = ffma2(td[i], wv.x, acc2[i][0]);
                acc2[i][1] = ffma2(td[i], wv.y, acc2[i][1]);
            }
        }
        float pl[4] = {0.f, 0.f, 0.f, 0.f};
#pragma unroll
        for (int jp = 0; jp < 2; ++jp) {
#pragma unroll
            for (int p = 0; p < 2; ++p) {
                const int j = j0 + 2 * jp + p;
                const float bb = sm[PB2 + j];
                const float al = sm[PA2 + j];
                const float wf = sm[PWF + j];
#pragma unroll
                for (int i = 0; i < 4; ++i) {
                    float2 v2 = unpk(acc2[i][jp]);
                    float x = (p == 0 ? v2.x : v2.y) + bb;
                    x = (x > 0.f) ? x : al * x;
                    pl[i] += x * wf;
                }
            }
        }
        *(float4*)&sm[PART + hh * T_ + t0] = make_float4(pl[0], pl[1], pl[2], pl[3]);
    }
    __syncthreads();

    // ------- Phase 4: logits+mask; k16 row-major fp16 copy; warp15 bucket scan -------
    if (tid < T_) {
        float s = bf[0];
#pragma unroll
        for (int g = 0; g < 10; ++g) s += sm[PART + g * T_ + tid];
        if (mask[b * T_ + tid] == 0) s = -4294967295.0f;   // -2^32 + 1
        sm[WGT + tid] = s * 0.125f;                         // / sqrt(64)
    }
    {   // k16[t][d] fp16 row-major: overwrites dead h1 region (GEMM2 done)
        const float4* k4 = (const float4*)(k + (size_t)b * T_ * D_);
        for (int idx = tid; idx < T_ * 16; idx += TPB) {
            float4 v = k4[idx];                 // L2-hit reload, fully coalesced
            const int t = idx >> 4, d0 = (idx & 15) << 2;
            __half2 a = __float22half2_rn(make_float2(v.x, v.y));
            __half2 c = __float22half2_rn(make_float2(v.z, v.w));
            *(uint2*)&k16[t * 64 + d0] = make_uint2(*(unsigned*)&a, *(unsigned*)&c);
        }
    }
    if (tid >= 480) {
        const int l = tid - 480;
        const int c0 = smi[CNT + 2 * l], c1 = smi[CNT + 2 * l + 1];
        int s = c0 + c1;
#pragma unroll
        for (int off = 1; off < 32; off <<= 1) {
            int n = __shfl_up_sync(0xffffffffu, s, off);
            if (l >= off) s += n;
        }
        const int excl = s - (c0 + c1);
        smi[BST + 2 * l] = excl;        smi[BST + 2 * l + 1] = excl + c0;
        smi[CNT2 + 2 * l] = excl;       smi[CNT2 + 2 * l + 1] = excl + c0;
    }
    __syncthreads();

    // ---------------- Phase 5: softmax over 200 ----------------
    {
        float v = (tid < T_) ? sm[WGT + tid] : -3.4e38f;
#pragma unroll
        for (int o = 16; o; o >>= 1) v = fmaxf(v, __shfl_xor_sync(0xffffffffu, v, o));
        if (lane == 0) sm[RED + warp] = v;
        __syncthreads();
        float mx = sm[RED + 0];
#pragma unroll
        for (int i = 1; i < 16; ++i) mx = fmaxf(mx, sm[RED + i]);
        float e = (tid < T_) ? __expf(sm[WGT + tid] - mx) : 0.f;
        float sv = e;
#pragma unroll
        for (int o = 16; o; o >>= 1) sv += __shfl_xor_sync(0xffffffffu, sv, o);
        if (lane == 0) sm[RED + 16 + warp] = sv;
        __syncthreads();
        float S = 0.f;
#pragma unroll
        for (int i = 0; i < 16; ++i) S += sm[RED + 16 + i];
        if (tid < T_) sm[WGT + tid] = e / S;
    }
    __syncthreads();

    // ---------------- Phase 5b+6: bucket scatter + user_interest partials ------------
    if (tid < T_) {
        const int c = smi[CATE + tid];
        const int pos = atomicAdd(&smi[CNT2 + c], 1);
        smi[TLIST + pos] = tid;
    }
    {
        const int d = tid & 63, g = tid >> 6;   // 8 groups x 25 t; conflict-free k16 reads
        float s = 0.f;
        const int tb = g * 25;
#pragma unroll 5
        for (int t = tb; t < tb + 25; ++t)
            s += sm[WGT + t] * __half2float(k16[t * 64 + d]);
        sm[PART + tid] = s;
    }
    __syncthreads();

    if (tid < D_) {
        float s = 0.f;
#pragma unroll
        for (int g = 0; g < 8; ++g) s += sm[PART + g * 64 + tid];
        out_ui[b * D_ + tid] = s;
    }

    // ---------------- Phase 7: bucketed per-category pooling (no atomics) ------------
    {
        const int g = tid >> 6, d = tid & 63;   // 8 groups of 64 lanes; 8 cats each
        float* ch = out_ch + (size_t)b * C_ * D_;
        for (int c = g; c < C_; c += 8) {
            const int len = smi[CNT + c];
            const int st  = smi[BST + c];
            float acc = 0.f, ws = 0.f;
            for (int i = 0; i < len; ++i) {
                const int t = smi[TLIST + st + i];
                const float w = sm[WGT + t];
                ws  += w;
                acc += w * __half2float(k16[t * 64 + d]);   // conflict-free row read
            }
            ch[c * D_ + d] = acc / (ws + 1e-10f);
        }
    }
}

extern "C" void kernel_launch(void* const* d_in, const int* in_sizes, int n_in,
                              void* d_out, int out_size)
{
    const float* q    = (const float*)d_in[0];
    const float* k    = (const float*)d_in[1];
    const int*   mask = (const int*)d_in[2];
    const int*   cate = (const int*)d_in[3];
    // d_in[4] = cate_count (compile-time C_=64)
    const float* W1 = (const float*)d_in[5];
    const float* b1 = (const float*)d_in[6];
    const float* a1 = (const float*)d_in[7];
    const float* W2 = (const float*)d_in[8];
    const float* b2 = (const float*)d_in[9];
    const float* a2 = (const float*)d_in[10];
    const float* Wf = (const float*)d_in[11];
    const float* bf = (const float*)d_in[12];

    const int B = in_sizes[0] / D_;
    float* out_ui = (float*)d_out;                     // [B, 64]
    float* out_ch = (float*)d_out + (size_t)B * D_;    // [B, 64, 64]

    cudaFuncSetAttribute(din_kernel, cudaFuncAttributeMaxDynamicSharedMemorySize, SMEM_BYTES);
    din_kernel<<<B, TPB, SMEM_BYTES>>>(q, k, mask, cate, W1, b1, a1, W2, b2, a2, Wf, bf,
                                       out_ui, out_ch);
}